// round 1
// baseline (speedup 1.0000x reference)
#include <cuda_runtime.h>
#include <cuda_bf16.h>

#define N_CTRL 64
#define N_EVAL 2001
#define DEG 3
// internal knots: (j-3)/61 for j in [4,63]
#define INV_INTERNAL (1.0f / 61.0f)

// ---------------- device scratch (no allocations allowed) ----------------
__device__ float4 g_cp4[N_CTRL * N_CTRL];   // control points packed xyz_
__device__ float4 g_Bu[N_EVAL];             // cubic basis along u
__device__ float4 g_Bv[N_EVAL];             // cubic basis along v
__device__ int    g_su[N_EVAL];
__device__ int    g_sv[N_EVAL];

// clamped uniform knot value, p=3, n_ctrl=64, length 68
__device__ __forceinline__ float knotf(int j) {
    if (j <= DEG) return 0.0f;
    if (j >= N_CTRL) return 1.0f;
    return (float)(j - DEG) * INV_INTERNAL;
}

// span = clip(searchsorted(knots, u, 'right') - 1, p, n_ctrl-1)
__device__ __forceinline__ int find_span(float u) {
    int span = DEG;
    #pragma unroll
    for (int j = DEG + 1; j <= N_CTRL - 1; ++j) {
        if (u >= knotf(j)) span = j;
    }
    return span;
}

// Cox-de-Boor (NURBS book A2.2), p=3, matches reference op order
__device__ __forceinline__ void basis_funcs(float u, int span, float N[4]) {
    float left[4], right[4];
    N[0] = 1.0f;
    #pragma unroll
    for (int j = 1; j <= DEG; ++j) {
        left[j]  = u - knotf(span + 1 - j);
        right[j] = knotf(span + j) - u;
        float saved = 0.0f;
        #pragma unroll
        for (int r = 0; r < j; ++r) {
            float temp = N[r] / (right[r + 1] + left[j - r]);
            N[r] = saved + right[r + 1] * temp;
            saved = left[j - r] * temp;
        }
        N[j] = saved;
    }
}

__global__ void nurbs_prep_kernel(const float* __restrict__ cp,
                                  const float* __restrict__ pu,
                                  const float* __restrict__ pv) {
    int i = blockIdx.x * blockDim.x + threadIdx.x;
    if (i < N_CTRL * N_CTRL) {
        g_cp4[i] = make_float4(cp[3 * i], cp[3 * i + 1], cp[3 * i + 2], 0.0f);
    }
    if (i < N_EVAL) {
        {
            float u = pu[i];
            int s = find_span(u);
            float B[4];
            basis_funcs(u, s, B);
            g_Bu[i] = make_float4(B[0], B[1], B[2], B[3]);
            g_su[i] = s;
        }
        {
            float v = pv[i];
            int s = find_span(v);
            float B[4];
            basis_funcs(v, s, B);
            g_Bv[i] = make_float4(B[0], B[1], B[2], B[3]);
            g_sv[i] = s;
        }
    }
}

// Eval: block = 128 threads, each thread computes 4 consecutive v points for
// one u row. Block tile = 512 v points. Stores staged through smem for
// perfectly coalesced global writes.
#define TPB 128
#define VPT 4
#define TILE_V (TPB * VPT)   // 512

__global__ __launch_bounds__(TPB) void nurbs_eval_kernel(float* __restrict__ out) {
    __shared__ float s_out[TILE_V * 3];

    const int u    = blockIdx.y;
    const int tid  = threadIdx.x;
    const int vblk = blockIdx.x * TILE_V;

    const float4 bu = g_Bu[u];
    const int    su = g_su[u];
    const int v0 = vblk + tid * VPT;

    int prev_sv = -1;
    float cv0x = 0, cv0y = 0, cv0z = 0;
    float cv1x = 0, cv1y = 0, cv1z = 0;
    float cv2x = 0, cv2y = 0, cv2z = 0;
    float cv3x = 0, cv3y = 0, cv3z = 0;

    #pragma unroll
    for (int k = 0; k < VPT; ++k) {
        int v = v0 + k;
        if (v < N_EVAL) {
            int sv = g_sv[v];
            if (sv != prev_sv) {
                prev_sv = sv;
                // collapse u-direction: cv[b] = sum_a bu[a] * cp[su-3+a, sv-3+b]
                const float4* base = g_cp4 + (su - DEG) * N_CTRL + (sv - DEG);
                #pragma unroll
                for (int b = 0; b < 4; ++b) {
                    float4 p0 = base[b];
                    float4 p1 = base[b + N_CTRL];
                    float4 p2 = base[b + 2 * N_CTRL];
                    float4 p3 = base[b + 3 * N_CTRL];
                    float cx = bu.x * p0.x + bu.y * p1.x + bu.z * p2.x + bu.w * p3.x;
                    float cy = bu.x * p0.y + bu.y * p1.y + bu.z * p2.y + bu.w * p3.y;
                    float cz = bu.x * p0.z + bu.y * p1.z + bu.z * p2.z + bu.w * p3.z;
                    if (b == 0) { cv0x = cx; cv0y = cy; cv0z = cz; }
                    if (b == 1) { cv1x = cx; cv1y = cy; cv1z = cz; }
                    if (b == 2) { cv2x = cx; cv2y = cy; cv2z = cz; }
                    if (b == 3) { cv3x = cx; cv3y = cy; cv3z = cz; }
                }
            }
            float4 bv = g_Bv[v];
            float x = bv.x * cv0x + bv.y * cv1x + bv.z * cv2x + bv.w * cv3x;
            float y = bv.x * cv0y + bv.y * cv1y + bv.z * cv2y + bv.w * cv3y;
            float z = bv.x * cv0z + bv.y * cv1z + bv.z * cv2z + bv.w * cv3z;
            int lo = (tid * VPT + k) * 3;
            s_out[lo + 0] = x;
            s_out[lo + 1] = y;
            s_out[lo + 2] = z;
        }
    }
    __syncthreads();

    // coalesced copy smem -> gmem
    const int gbase = (u * N_EVAL + vblk) * 3;
    const int nv    = (N_EVAL - vblk) < TILE_V ? (N_EVAL - vblk) : TILE_V;
    const int cnt   = nv * 3;
    #pragma unroll
    for (int i = tid; i < cnt; i += TPB) {
        out[gbase + i] = s_out[i];
    }
}

extern "C" void kernel_launch(void* const* d_in, const int* in_sizes, int n_in,
                              void* d_out, int out_size) {
    const float* cp = (const float*)d_in[0];   // [64,64,3]
    const float* pu = (const float*)d_in[1];   // [2001]
    const float* pv = (const float*)d_in[2];   // [2001]
    // d_in[3] = degree (int), fixed at 3
    float* out = (float*)d_out;

    {
        int n = N_CTRL * N_CTRL;  // 4096 >= 2001
        nurbs_prep_kernel<<<(n + 255) / 256, 256>>>(cp, pu, pv);
    }
    {
        dim3 grid((N_EVAL + TILE_V - 1) / TILE_V, N_EVAL);
        nurbs_eval_kernel<<<grid, TPB>>>(out);
    }
}

// round 2
// speedup vs baseline: 1.5586x; 1.5586x over previous
#include <cuda_runtime.h>
#include <cuda_bf16.h>

#define N_CTRL 64
#define N_EVAL 2001
#define DEG 3
#define INV_INTERNAL (1.0f / 61.0f)

// ---------------- device scratch (no allocations allowed) ----------------
__device__ float4 g_cp4[N_CTRL * N_CTRL];        // control points packed xyz_
__device__ float4 g_Bu[N_EVAL];                  // cubic basis along u
__device__ float4 g_Bv[N_EVAL];                  // cubic basis along v
__device__ int    g_su[N_EVAL];
__device__ int    g_sv[N_EVAL];
__device__ float4 g_curve[N_EVAL * N_CTRL];      // u-collapsed curves [u][j], 2 MB

// clamped uniform knot value, p=3, n_ctrl=64, length 68
__device__ __forceinline__ float knotf(int j) {
    if (j <= DEG) return 0.0f;
    if (j >= N_CTRL) return 1.0f;
    return (float)(j - DEG) * INV_INTERNAL;
}

// span = clip(searchsorted(knots, u, 'right') - 1, p, n_ctrl-1)
__device__ __forceinline__ int find_span(float u) {
    int span = DEG;
    #pragma unroll
    for (int j = DEG + 1; j <= N_CTRL - 1; ++j) {
        if (u >= knotf(j)) span = j;
    }
    return span;
}

// Cox-de-Boor (NURBS book A2.2), p=3, matches reference op order
__device__ __forceinline__ void basis_funcs(float u, int span, float N[4]) {
    float left[4], right[4];
    N[0] = 1.0f;
    #pragma unroll
    for (int j = 1; j <= DEG; ++j) {
        left[j]  = u - knotf(span + 1 - j);
        right[j] = knotf(span + j) - u;
        float saved = 0.0f;
        #pragma unroll
        for (int r = 0; r < j; ++r) {
            float temp = N[r] / (right[r + 1] + left[j - r]);
            N[r] = saved + right[r + 1] * temp;
            saved = left[j - r] * temp;
        }
        N[j] = saved;
    }
}

// ---------------- kernel 1: spans + basis + cp packing ----------------
__global__ void nurbs_prep_kernel(const float* __restrict__ cp,
                                  const float* __restrict__ pu,
                                  const float* __restrict__ pv) {
    int i = blockIdx.x * blockDim.x + threadIdx.x;
    if (i < N_CTRL * N_CTRL) {
        g_cp4[i] = make_float4(cp[3 * i], cp[3 * i + 1], cp[3 * i + 2], 0.0f);
    }
    if (i < N_EVAL) {
        {
            float u = pu[i];
            int s = find_span(u);
            float B[4];
            basis_funcs(u, s, B);
            g_Bu[i] = make_float4(B[0], B[1], B[2], B[3]);
            g_su[i] = s;
        }
        {
            float v = pv[i];
            int s = find_span(v);
            float B[4];
            basis_funcs(v, s, B);
            g_Bv[i] = make_float4(B[0], B[1], B[2], B[3]);
            g_sv[i] = s;
        }
    }
}

// ---------------- kernel 2: u-collapse -> curve_u[u][j] ----------------
// curve[u][j] = sum_a Bu[u][a] * cp[su(u)-3+a][j]   (reference's curve_u einsum)
__global__ __launch_bounds__(256) void nurbs_collapse_kernel() {
    int idx = blockIdx.x * blockDim.x + threadIdx.x;
    if (idx >= N_EVAL * N_CTRL) return;
    int u = idx >> 6;       // /64
    int j = idx & 63;       // %64

    float4 bu = g_Bu[u];    // broadcast within 64-lane groups
    int    su = g_su[u];

    const float4* base = g_cp4 + (su - DEG) * N_CTRL + j;  // coalesced across j
    float4 p0 = base[0];
    float4 p1 = base[N_CTRL];
    float4 p2 = base[2 * N_CTRL];
    float4 p3 = base[3 * N_CTRL];

    float4 c;
    c.x = bu.x * p0.x + bu.y * p1.x + bu.z * p2.x + bu.w * p3.x;
    c.y = bu.x * p0.y + bu.y * p1.y + bu.z * p2.y + bu.w * p3.y;
    c.z = bu.x * p0.z + bu.y * p1.z + bu.z * p2.z + bu.w * p3.z;
    c.w = 0.0f;
    g_curve[idx] = c;
}

// ---------------- kernel 3: v-direction eval, one block per u row ----------------
#define TPB 256
#define ROW_FLOATS (N_EVAL * 3)   // 6003

__global__ __launch_bounds__(TPB) void nurbs_eval_kernel(float* __restrict__ out) {
    __shared__ float4 s_curve[N_CTRL];          // 1 KB: this row's collapsed curve
    __shared__ float  s_out[ROW_FLOATS + 13];   // 24 KB staging (pad)

    const int u   = blockIdx.x;
    const int tid = threadIdx.x;

    // cooperative load of curve row (64 float4, coalesced)
    if (tid < N_CTRL) {
        s_curve[tid] = g_curve[u * N_CTRL + tid];
    }
    __syncthreads();

    // each lane computes strided points; neighbors in a warp are adjacent v
    #pragma unroll 2
    for (int p = tid; p < N_EVAL; p += TPB) {
        float4 bv = g_Bv[p];                    // coalesced LDG.128
        int    sv = g_sv[p];                    // coalesced LDG.32
        const float4* c = s_curve + (sv - DEG); // broadcast-friendly LDS
        float4 c0 = c[0];
        float4 c1 = c[1];
        float4 c2 = c[2];
        float4 c3 = c[3];
        float x = bv.x * c0.x + bv.y * c1.x + bv.z * c2.x + bv.w * c3.x;
        float y = bv.x * c0.y + bv.y * c1.y + bv.z * c2.y + bv.w * c3.y;
        float z = bv.x * c0.z + bv.y * c1.z + bv.z * c2.z + bv.w * c3.z;
        int lo = p * 3;                         // stride-3: bank-conflict-free
        s_out[lo + 0] = x;
        s_out[lo + 1] = y;
        s_out[lo + 2] = z;
    }
    __syncthreads();

    // coalesced copy smem -> gmem
    float* dst = out + (size_t)u * ROW_FLOATS;
    #pragma unroll 4
    for (int i = tid; i < ROW_FLOATS; i += TPB) {
        dst[i] = s_out[i];
    }
}

extern "C" void kernel_launch(void* const* d_in, const int* in_sizes, int n_in,
                              void* d_out, int out_size) {
    const float* cp = (const float*)d_in[0];   // [64,64,3]
    const float* pu = (const float*)d_in[1];   // [2001]
    const float* pv = (const float*)d_in[2];   // [2001]
    float* out = (float*)d_out;

    {
        int n = N_CTRL * N_CTRL;  // 4096 >= 2001
        nurbs_prep_kernel<<<(n + 255) / 256, 256>>>(cp, pu, pv);
    }
    {
        int n = N_EVAL * N_CTRL;  // 128064
        nurbs_collapse_kernel<<<(n + 255) / 256, 256>>>();
    }
    {
        nurbs_eval_kernel<<<N_EVAL, TPB>>>(out);
    }
}

// round 3
// speedup vs baseline: 1.8122x; 1.1627x over previous
#include <cuda_runtime.h>
#include <cuda_bf16.h>

#define N_CTRL 64
#define N_EVAL 2001
#define DEG 3
#define INV_INTERNAL (1.0f / 61.0f)   // 60 internal knots at k/61, k=1..60

// ---------------- device scratch (no allocations allowed) ----------------
__device__ float4 g_Bu[N_EVAL];   // cubic basis along u
__device__ float4 g_Bv[N_EVAL];   // cubic basis along v
__device__ int    g_su[N_EVAL];
__device__ int    g_sv[N_EVAL];

// clamped uniform knot value, p=3, n_ctrl=64, knot vector length 68
__device__ __forceinline__ float knotf(int j) {
    if (j <= DEG) return 0.0f;
    if (j >= N_CTRL) return 1.0f;
    return (float)(j - DEG) * INV_INTERNAL;
}

// span = clip(searchsorted(knots, t, 'right') - 1, p, n_ctrl-1), analytic.
// Internal knot values are k * (1/61); fixups use the SAME float expressions
// as knotf() so comparisons are bit-consistent with the basis evaluation.
__device__ __forceinline__ int find_span(float t) {
    int k = (int)floorf(t * 61.0f);
    if (k < 0) k = 0;
    if (k > 60) k = 60;
    // count of internal knots <= t must be exact under float compare:
    if (k < 60 && (float)(k + 1) * INV_INTERNAL <= t) ++k;
    if (k > 0  && (float)k * INV_INTERNAL > t)        --k;
    return DEG + k;   // in [3, 63]
}

// Cox-de-Boor (NURBS book A2.2), p=3, same op order as reference
__device__ __forceinline__ void basis_funcs(float u, int span, float N[4]) {
    float left[4], right[4];
    N[0] = 1.0f;
    #pragma unroll
    for (int j = 1; j <= DEG; ++j) {
        left[j]  = u - knotf(span + 1 - j);
        right[j] = knotf(span + j) - u;
        float saved = 0.0f;
        #pragma unroll
        for (int r = 0; r < j; ++r) {
            float temp = N[r] / (right[r + 1] + left[j - r]);
            N[r] = saved + right[r + 1] * temp;
            saved = left[j - r] * temp;
        }
        N[j] = saved;
    }
}

// ---------------- kernel 1: spans + basis for both axes (tiny) ----------------
__global__ void nurbs_prep_kernel(const float* __restrict__ pu,
                                  const float* __restrict__ pv) {
    int i = blockIdx.x * blockDim.x + threadIdx.x;
    if (i >= N_EVAL) return;
    {
        float u = pu[i];
        int s = find_span(u);
        float B[4];
        basis_funcs(u, s, B);
        g_Bu[i] = make_float4(B[0], B[1], B[2], B[3]);
        g_su[i] = s;
    }
    {
        float v = pv[i];
        int s = find_span(v);
        float B[4];
        basis_funcs(v, s, B);
        g_Bv[i] = make_float4(B[0], B[1], B[2], B[3]);
        g_sv[i] = s;
    }
}

// ---------------- kernel 2: fused collapse + v-eval, one block per u row ----------------
#define TPB 256
#define ROW_FLOATS (N_EVAL * 3)   // 6003

__global__ __launch_bounds__(TPB) void nurbs_eval_kernel(const float* __restrict__ cp,
                                                         float* __restrict__ out) {
    __shared__ float4 s_curve[N_CTRL];          // 1 KB: u-collapsed curve row
    __shared__ float  s_out[ROW_FLOATS + 13];   // 24 KB store staging

    const int u   = blockIdx.x;
    const int tid = threadIdx.x;

    const float4 bu = g_Bu[u];   // broadcast load, L1-hot
    const int    su = g_su[u];

    // collapse u-direction in-block:
    // s_curve[j] = sum_a bu[a] * cp[su-3+a][j]   (reference's curve_u einsum)
    if (tid < N_CTRL) {
        const float* base = cp + ((su - DEG) * N_CTRL + tid) * 3;
        float cx = 0.f, cy = 0.f, cz = 0.f;
        float w[4] = {bu.x, bu.y, bu.z, bu.w};
        #pragma unroll
        for (int a = 0; a < 4; ++a) {
            const float* q = base + a * (N_CTRL * 3);
            cx += w[a] * q[0];
            cy += w[a] * q[1];
            cz += w[a] * q[2];
        }
        s_curve[tid] = make_float4(cx, cy, cz, 0.f);
    }
    __syncthreads();

    // v-direction eval; adjacent lanes handle adjacent v (coalesced Bv/sv)
    #pragma unroll 2
    for (int p = tid; p < N_EVAL; p += TPB) {
        float4 bv = g_Bv[p];
        int    sv = g_sv[p];
        const float4* c = s_curve + (sv - DEG);
        float4 c0 = c[0];
        float4 c1 = c[1];
        float4 c2 = c[2];
        float4 c3 = c[3];
        float x = bv.x * c0.x + bv.y * c1.x + bv.z * c2.x + bv.w * c3.x;
        float y = bv.x * c0.y + bv.y * c1.y + bv.z * c2.y + bv.w * c3.y;
        float z = bv.x * c0.z + bv.y * c1.z + bv.z * c2.z + bv.w * c3.z;
        int lo = p * 3;                         // stride-3: conflict-free STS
        s_out[lo + 0] = x;
        s_out[lo + 1] = y;
        s_out[lo + 2] = z;
    }
    __syncthreads();

    // coalesced copy smem -> gmem (minimum store wavefronts)
    float* dst = out + (size_t)u * ROW_FLOATS;
    #pragma unroll 4
    for (int i = tid; i < ROW_FLOATS; i += TPB) {
        dst[i] = s_out[i];
    }
}

extern "C" void kernel_launch(void* const* d_in, const int* in_sizes, int n_in,
                              void* d_out, int out_size) {
    const float* cp = (const float*)d_in[0];   // [64,64,3]
    const float* pu = (const float*)d_in[1];   // [2001]
    const float* pv = (const float*)d_in[2];   // [2001]
    float* out = (float*)d_out;

    nurbs_prep_kernel<<<(N_EVAL + 255) / 256, 256>>>(pu, pv);
    nurbs_eval_kernel<<<N_EVAL, TPB>>>(cp, out);
}

// round 4
// speedup vs baseline: 2.2047x; 1.2166x over previous
#include <cuda_runtime.h>
#include <cuda_bf16.h>

#define N_CTRL 64
#define N_EVAL 2001
#define DEG 3
#define INV_INTERNAL (1.0f / 61.0f)   // 60 internal knots at k/61, k=1..60

// ---------------- device scratch (no allocations allowed) ----------------
__device__ float4 g_Bu[N_EVAL];   // cubic basis along u
__device__ float4 g_Bv[N_EVAL];   // cubic basis along v
__device__ int    g_su[N_EVAL];
__device__ int    g_sv[N_EVAL];

// clamped uniform knot value, p=3, n_ctrl=64, knot vector length 68
__device__ __forceinline__ float knotf(int j) {
    if (j <= DEG) return 0.0f;
    if (j >= N_CTRL) return 1.0f;
    return (float)(j - DEG) * INV_INTERNAL;
}

// span = clip(searchsorted(knots, t, 'right') - 1, p, n_ctrl-1), analytic.
__device__ __forceinline__ int find_span(float t) {
    int k = (int)floorf(t * 61.0f);
    if (k < 0) k = 0;
    if (k > 60) k = 60;
    if (k < 60 && (float)(k + 1) * INV_INTERNAL <= t) ++k;
    if (k > 0  && (float)k * INV_INTERNAL > t)        --k;
    return DEG + k;   // in [3, 63]
}

// Cox-de-Boor (NURBS book A2.2), p=3, same op order as reference
__device__ __forceinline__ void basis_funcs(float u, int span, float N[4]) {
    float left[4], right[4];
    N[0] = 1.0f;
    #pragma unroll
    for (int j = 1; j <= DEG; ++j) {
        left[j]  = u - knotf(span + 1 - j);
        right[j] = knotf(span + j) - u;
        float saved = 0.0f;
        #pragma unroll
        for (int r = 0; r < j; ++r) {
            float temp = N[r] / (right[r + 1] + left[j - r]);
            N[r] = saved + right[r + 1] * temp;
            saved = left[j - r] * temp;
        }
        N[j] = saved;
    }
}

// ---------------- kernel 1: spans + basis for both axes (tiny) ----------------
__global__ void nurbs_prep_kernel(const float* __restrict__ pu,
                                  const float* __restrict__ pv) {
    int i = blockIdx.x * blockDim.x + threadIdx.x;
    if (i >= N_EVAL) return;
    {
        float u = pu[i];
        int s = find_span(u);
        float B[4];
        basis_funcs(u, s, B);
        g_Bu[i] = make_float4(B[0], B[1], B[2], B[3]);
        g_su[i] = s;
    }
    {
        float v = pv[i];
        int s = find_span(v);
        float B[4];
        basis_funcs(v, s, B);
        g_Bv[i] = make_float4(B[0], B[1], B[2], B[3]);
        g_sv[i] = s;
    }
}

// ---------------- kernel 2: fused collapse + v-eval, 4 u-rows per block ----------------
#define TPB 256
#define U_TILE 4

__global__ __launch_bounds__(TPB) void nurbs_eval_kernel(const float* __restrict__ cp,
                                                         float* __restrict__ out) {
    __shared__ float4 s_curve[U_TILE][N_CTRL];   // 4 KB

    const int u0  = blockIdx.x * U_TILE;
    const int tid = threadIdx.x;
    const int nrows = (N_EVAL - u0) < U_TILE ? (N_EVAL - u0) : U_TILE;

    // cooperative u-collapse: tid -> (row r, ctrl col j); 256 = 4*64 exact
    {
        const int r = tid >> 6;        // 0..3
        const int j = tid & 63;        // 0..63
        if (r < nrows) {
            const float4 bu = g_Bu[u0 + r];
            const int    su = g_su[u0 + r];
            const float* base = cp + ((su - DEG) * N_CTRL + j) * 3;
            float w[4] = {bu.x, bu.y, bu.z, bu.w};
            float cx = 0.f, cy = 0.f, cz = 0.f;
            #pragma unroll
            for (int a = 0; a < 4; ++a) {
                const float* q = base + a * (N_CTRL * 3);
                cx += w[a] * q[0];
                cy += w[a] * q[1];
                cz += w[a] * q[2];
            }
            s_curve[r][j] = make_float4(cx, cy, cz, 0.f);
        }
    }
    __syncthreads();

    // v eval: adjacent lanes -> adjacent v (coalesced Bv/sv); direct stores
    for (int p = tid; p < N_EVAL; p += TPB) {
        const float4 bv = g_Bv[p];
        const int    o  = g_sv[p] - DEG;
        #pragma unroll
        for (int r = 0; r < U_TILE; ++r) {
            if (r < nrows) {
                const float4 c0 = s_curve[r][o + 0];
                const float4 c1 = s_curve[r][o + 1];
                const float4 c2 = s_curve[r][o + 2];
                const float4 c3 = s_curve[r][o + 3];
                float x = bv.x * c0.x + bv.y * c1.x + bv.z * c2.x + bv.w * c3.x;
                float y = bv.x * c0.y + bv.y * c1.y + bv.z * c2.y + bv.w * c3.y;
                float z = bv.x * c0.z + bv.y * c1.z + bv.z * c2.z + bv.w * c3.z;
                float* dst = out + ((size_t)(u0 + r) * N_EVAL + p) * 3;
                dst[0] = x;
                dst[1] = y;
                dst[2] = z;
            }
        }
    }
}

extern "C" void kernel_launch(void* const* d_in, const int* in_sizes, int n_in,
                              void* d_out, int out_size) {
    const float* cp = (const float*)d_in[0];   // [64,64,3]
    const float* pu = (const float*)d_in[1];   // [2001]
    const float* pv = (const float*)d_in[2];   // [2001]
    float* out = (float*)d_out;

    nurbs_prep_kernel<<<(N_EVAL + 255) / 256, 256>>>(pu, pv);
    nurbs_eval_kernel<<<(N_EVAL + U_TILE - 1) / U_TILE, TPB>>>(cp, out);
}